// round 3
// baseline (speedup 1.0000x reference)
#include <cuda_runtime.h>
#include <math.h>

// Problem constants (fixed by setup_inputs)
#define BQ   8
#define SEQ  1024
#define CH   512
#define HIDC 2048
#define NHD  8
#define HDIM 64
#define ROWS (BQ*SEQ)          // 8192
#define QKVW (3*CH)            // 1536

// ---------------- scratch (device globals; no allocations allowed) ---------
__device__ float g_ln [ROWS*CH];                     // 16 MB
__device__ float g_qkv[ROWS*QKVW];                   // 50 MB
__device__ float g_at [ROWS*CH];                     // 16 MB
__device__ float g_x1 [ROWS*CH];                     // 16 MB
__device__ float g_h  [ROWS*HIDC];                   // 64 MB
__device__ float g_h2 [ROWS*HIDC];                   // 64 MB

// ---------------- LayerNorm: one block (128 thr) per row of 512 ------------
__global__ void ln_kernel(const float* __restrict__ x,
                          const float* __restrict__ g,
                          const float* __restrict__ b,
                          float* __restrict__ out)
{
    int row = blockIdx.x;
    const float* xr = x + (size_t)row * CH;
    float*       orow = out + (size_t)row * CH;
    int t = threadIdx.x;                 // 128 threads, 4 elems each
    float v[4];
    float s = 0.f;
#pragma unroll
    for (int i = 0; i < 4; i++) { v[i] = xr[t + i*128]; s += v[i]; }
    __shared__ float red[4];
#pragma unroll
    for (int o = 16; o > 0; o >>= 1) s += __shfl_xor_sync(0xffffffffu, s, o);
    if ((t & 31) == 0) red[t >> 5] = s;
    __syncthreads();
    float mean = (red[0] + red[1] + red[2] + red[3]) * (1.0f / CH);
    float vs = 0.f;
#pragma unroll
    for (int i = 0; i < 4; i++) { float d = v[i] - mean; vs += d * d; }
#pragma unroll
    for (int o = 16; o > 0; o >>= 1) vs += __shfl_xor_sync(0xffffffffu, vs, o);
    __syncthreads();
    if ((t & 31) == 0) red[t >> 5] = vs;
    __syncthreads();
    float var = (red[0] + red[1] + red[2] + red[3]) * (1.0f / CH);
    float rstd = rsqrtf(var + 1e-5f);
#pragma unroll
    for (int i = 0; i < 4; i++) {
        int c = t + i*128;
        orow[c] = (v[i] - mean) * rstd * g[c] + b[c];
    }
}

// ---------------- Generic SGEMM (weights): out = A @ B^T -------------------
// out[m,n] = sum_k A[m,k] * B[n,k]  (+bias[n]) (+res[m,n])
#define TBM 64
#define TBN 64
#define TBK 16

__global__ __launch_bounds__(256)
void gemm_kernel(const float* __restrict__ A, int lda,
                 const float* __restrict__ Bm, int ldb,
                 const float* __restrict__ bias,
                 const float* __restrict__ res, int ldres,
                 float* __restrict__ out, int ldo,
                 int K)
{
    int m0 = blockIdx.y * TBM;
    int n0 = blockIdx.x * TBN;

    __shared__ __align__(16) float As[TBK][TBM];
    __shared__ __align__(16) float Bs[TBK][TBN];

    int tid = threadIdx.x;
    int ty = tid >> 4, tx = tid & 15;     // 16x16 threads, 4x4 micro-tile
    float acc[4][4] = {};

    int lm = tid >> 2;                    // 0..63
    int kq = (tid & 3) * 4;               // 0,4,8,12

    for (int k0 = 0; k0 < K; k0 += TBK) {
        float4 a4 = *(const float4*)(A + (size_t)(m0 + lm) * lda + k0 + kq);
        As[kq + 0][lm] = a4.x; As[kq + 1][lm] = a4.y;
        As[kq + 2][lm] = a4.z; As[kq + 3][lm] = a4.w;
        float4 b4 = *(const float4*)(Bm + (size_t)(n0 + lm) * ldb + k0 + kq);
        Bs[kq + 0][lm] = b4.x; Bs[kq + 1][lm] = b4.y;
        Bs[kq + 2][lm] = b4.z; Bs[kq + 3][lm] = b4.w;
        __syncthreads();
#pragma unroll
        for (int k = 0; k < TBK; k++) {
            float4 av = *(const float4*)&As[k][ty * 4];
            float4 bv = *(const float4*)&Bs[k][tx * 4];
            float a[4] = {av.x, av.y, av.z, av.w};
            float bb[4] = {bv.x, bv.y, bv.z, bv.w};
#pragma unroll
            for (int i = 0; i < 4; i++)
#pragma unroll
                for (int j = 0; j < 4; j++)
                    acc[i][j] += a[i] * bb[j];
        }
        __syncthreads();
    }

#pragma unroll
    for (int i = 0; i < 4; i++) {
        int m = m0 + ty * 4 + i;
#pragma unroll
        for (int j = 0; j < 4; j++) {
            int n = n0 + tx * 4 + j;
            float v = acc[i][j];
            if (bias) v += bias[n];
            if (res)  v += res[(size_t)m * ldres + n];
            out[(size_t)m * ldo + n] = v;
        }
    }
}

// ---------------- Fused flash attention ------------------------------------
// grid: (SEQ/64, BQ*NHD); 256 threads; one CTA owns 64 queries of one head.
// qkv row layout: head h occupies cols [h*192, h*192+192) = [q|k|v] of 64 each.
#define PADW 68
// smem offsets (floats)
#define OFF_Q  0
#define OFF_K  (64*PADW)
#define OFF_P  (2*64*PADW)
#define OFF_V  (3*64*PADW)
#define FLASH_SMEM_BYTES ((3*64*PADW + 64*64)*4)

__global__ __launch_bounds__(256)
void flash_kernel(const float* __restrict__ qkv, float* __restrict__ out)
{
    extern __shared__ float sm[];
    float* Qs = sm + OFF_Q;   // [d][q]  stride PADW
    float* Ks = sm + OFF_K;   // [d][n]  stride PADW
    float* Pt = sm + OFF_P;   // [k][q]  stride PADW
    float* Vs = sm + OFF_V;   // [k][d]  stride 64

    int bz = blockIdx.y;
    int bI = bz / NHD, hI = bz % NHD;
    int q0 = blockIdx.x * 64;
    const float* base = qkv + (size_t)bI * SEQ * QKVW + hI * 3 * HDIM;

    int tid = threadIdx.x;
    int ty = tid >> 4, tx = tid & 15;
    int lm = tid >> 2;                 // 0..63 (row within tile)
    int kq = (tid & 3) * 4;            // 0,4,8,12 (d offset quarter)

    // load Q tile transposed: Qs[d][q]
#pragma unroll
    for (int r = 0; r < 4; r++) {
        int d = kq + r * 16;
        float4 a4 = *(const float4*)(base + (size_t)(q0 + lm) * QKVW + d);
        Qs[(d + 0) * PADW + lm] = a4.x; Qs[(d + 1) * PADW + lm] = a4.y;
        Qs[(d + 2) * PADW + lm] = a4.z; Qs[(d + 3) * PADW + lm] = a4.w;
    }

    float m[4], l[4], o[4][4];
#pragma unroll
    for (int i = 0; i < 4; i++) {
        m[i] = -1e30f; l[i] = 0.f;
#pragma unroll
        for (int j = 0; j < 4; j++) o[i][j] = 0.f;
    }

    for (int t0 = 0; t0 < SEQ; t0 += 64) {
        __syncthreads();   // previous PV done before overwriting Ks/Vs
        // load K tile transposed, V tile natural
#pragma unroll
        for (int r = 0; r < 4; r++) {
            int d = kq + r * 16;
            float4 k4 = *(const float4*)(base + (size_t)(t0 + lm) * QKVW + HDIM + d);
            Ks[(d + 0) * PADW + lm] = k4.x; Ks[(d + 1) * PADW + lm] = k4.y;
            Ks[(d + 2) * PADW + lm] = k4.z; Ks[(d + 3) * PADW + lm] = k4.w;
            float4 v4 = *(const float4*)(base + (size_t)(t0 + lm) * QKVW + 2 * HDIM + d);
            *(float4*)&Vs[lm * 64 + d] = v4;
        }
        __syncthreads();

        // S = (Q @ K^T) * 0.125  (64q x 64k), 4x4 micro-tile
        float s[4][4] = {};
#pragma unroll
        for (int kk = 0; kk < 64; kk++) {
            float4 qv = *(const float4*)&Qs[kk * PADW + ty * 4];
            float4 kv = *(const float4*)&Ks[kk * PADW + tx * 4];
            float qa[4] = {qv.x, qv.y, qv.z, qv.w};
            float kb[4] = {kv.x, kv.y, kv.z, kv.w};
#pragma unroll
            for (int i = 0; i < 4; i++)
#pragma unroll
                for (int j = 0; j < 4; j++)
                    s[i][j] += qa[i] * kb[j];
        }

        // online softmax
        float rmax[4], rsum[4];
#pragma unroll
        for (int i = 0; i < 4; i++) {
            float mx = s[i][0];
#pragma unroll
            for (int j = 1; j < 4; j++) mx = fmaxf(mx, s[i][j]);
            rmax[i] = mx * 0.125f;
        }
#pragma unroll
        for (int msk = 1; msk < 16; msk <<= 1)
#pragma unroll
            for (int i = 0; i < 4; i++)
                rmax[i] = fmaxf(rmax[i], __shfl_xor_sync(0xffffffffu, rmax[i], msk));

#pragma unroll
        for (int i = 0; i < 4; i++) {
            float mnew = fmaxf(m[i], rmax[i]);
            float scale = __expf(m[i] - mnew);
            m[i] = mnew;
            l[i] *= scale;
            float su = 0.f;
#pragma unroll
            for (int j = 0; j < 4; j++) {
                float p = __expf(s[i][j] * 0.125f - mnew);
                s[i][j] = p;
                su += p;
            }
            rsum[i] = su;
#pragma unroll
            for (int j = 0; j < 4; j++) o[i][j] *= scale;
        }
#pragma unroll
        for (int msk = 1; msk < 16; msk <<= 1)
#pragma unroll
            for (int i = 0; i < 4; i++)
                rsum[i] += __shfl_xor_sync(0xffffffffu, rsum[i], msk);
#pragma unroll
        for (int i = 0; i < 4; i++) l[i] += rsum[i];

        // write P transposed: Pt[k][q]
#pragma unroll
        for (int i = 0; i < 4; i++)
#pragma unroll
            for (int j = 0; j < 4; j++)
                Pt[(tx * 4 + j) * PADW + ty * 4 + i] = s[i][j];
        __syncthreads();

        // O += P @ V  (red over 64 keys)
#pragma unroll
        for (int kk = 0; kk < 64; kk++) {
            float4 pv = *(const float4*)&Pt[kk * PADW + ty * 4];
            float4 vv = *(const float4*)&Vs[kk * 64 + tx * 4];
            float pa[4] = {pv.x, pv.y, pv.z, pv.w};
            float vb[4] = {vv.x, vv.y, vv.z, vv.w};
#pragma unroll
            for (int i = 0; i < 4; i++)
#pragma unroll
                for (int j = 0; j < 4; j++)
                    o[i][j] += pa[i] * vb[j];
        }
    }

    // write O / l to g_at laid out as [B*SEQ, CH] with head offset
#pragma unroll
    for (int i = 0; i < 4; i++) {
        int q = q0 + ty * 4 + i;
        float inv = 1.0f / l[i];
        float* op = out + ((size_t)bI * SEQ + q) * CH + hI * HDIM + tx * 4;
#pragma unroll
        for (int j = 0; j < 4; j++) op[j] = o[i][j] * inv;
    }
}

// ---------------- Depthwise 3x3 conv + exact GELU --------------------------
__global__ void dwgelu_kernel(const float* __restrict__ h,
                              const float* __restrict__ w,
                              const float* __restrict__ bias,
                              float* __restrict__ out)
{
    int c = blockIdx.x * 256 + threadIdx.x;   // 0..2047
    int n = blockIdx.y;                       // 0..1023
    int b = blockIdx.z;                       // 0..7
    int hh = n >> 5, ww = n & 31;
    float acc = bias[c];
#pragma unroll
    for (int dy = -1; dy <= 1; dy++) {
        int y = hh + dy;
        if (y < 0 || y >= 32) continue;
#pragma unroll
        for (int dx = -1; dx <= 1; dx++) {
            int xw = ww + dx;
            if (xw < 0 || xw >= 32) continue;
            acc += h[((size_t)b * SEQ + y * 32 + xw) * HIDC + c]
                 * w[c * 9 + (dy + 1) * 3 + (dx + 1)];
        }
    }
    float gv = 0.5f * acc * (1.0f + erff(acc * 0.70710678118654752f));
    out[((size_t)b * SEQ + n) * HIDC + c] = gv;
}

// ---------------- launch ----------------------------------------------------
extern "C" void kernel_launch(void* const* d_in, const int* in_sizes, int n_in,
                              void* d_out, int out_size)
{
    const float* x      = (const float*)d_in[0];
    const float* ln1_g  = (const float*)d_in[1];
    const float* ln1_b  = (const float*)d_in[2];
    const float* qkv_w  = (const float*)d_in[3];
    const float* proj_w = (const float*)d_in[4];
    const float* proj_b = (const float*)d_in[5];
    const float* ln2_g  = (const float*)d_in[6];
    const float* ln2_b  = (const float*)d_in[7];
    const float* fc1_w  = (const float*)d_in[8];
    const float* fc1_b  = (const float*)d_in[9];
    const float* dw_w   = (const float*)d_in[10];
    const float* dw_b   = (const float*)d_in[11];
    const float* fc2_w  = (const float*)d_in[12];
    const float* fc2_b  = (const float*)d_in[13];
    float* out = (float*)d_out;

    float *lnb, *qkvb, *atb, *x1b, *hb, *h2b;
    cudaGetSymbolAddress((void**)&lnb,  g_ln);
    cudaGetSymbolAddress((void**)&qkvb, g_qkv);
    cudaGetSymbolAddress((void**)&atb,  g_at);
    cudaGetSymbolAddress((void**)&x1b,  g_x1);
    cudaGetSymbolAddress((void**)&hb,   g_h);
    cudaGetSymbolAddress((void**)&h2b,  g_h2);

    cudaFuncSetAttribute(flash_kernel,
                         cudaFuncAttributeMaxDynamicSharedMemorySize,
                         FLASH_SMEM_BYTES);

    // 1) LN1
    ln_kernel<<<ROWS, 128>>>(x, ln1_g, ln1_b, lnb);

    // 2) QKV GEMM: [8192,1536] = ln @ qkv_w^T
    gemm_kernel<<<dim3(QKVW/TBN, ROWS/TBM), 256>>>(
        lnb, CH, qkv_w, CH, nullptr, nullptr, 0, qkvb, QKVW, CH);

    // 3) fused attention -> atb [8192, 512]
    flash_kernel<<<dim3(SEQ/64, BQ*NHD), 256, FLASH_SMEM_BYTES>>>(qkvb, atb);

    // 4) x1 = x + o @ proj_w^T + proj_b
    gemm_kernel<<<dim3(CH/TBN, ROWS/TBM), 256>>>(
        atb, CH, proj_w, CH, proj_b, x, CH, x1b, CH, CH);

    // 5) LN2
    ln_kernel<<<ROWS, 128>>>(x1b, ln2_g, ln2_b, lnb);

    // 6) h = ln2 @ fc1_w^T + fc1_b
    gemm_kernel<<<dim3(HIDC/TBN, ROWS/TBM), 256>>>(
        lnb, CH, fc1_w, CH, fc1_b, nullptr, 0, hb, HIDC, CH);

    // 7) depthwise conv 3x3 + bias + exact gelu
    dwgelu_kernel<<<dim3(HIDC/256, SEQ, BQ), 256>>>(hb, dw_w, dw_b, h2b);

    // 8) out = x1 + h2 @ fc2_w^T + fc2_b
    gemm_kernel<<<dim3(CH/TBN, ROWS/TBM), 256>>>(
        h2b, HIDC, fc2_w, HIDC, fc2_b, x1b, CH, out, CH, HIDC);
}

// round 7
// speedup vs baseline: 1.3776x; 1.3776x over previous
#include <cuda_runtime.h>
#include <mma.h>
#include <math.h>
#include <stdint.h>

using namespace nvcuda;

// Problem constants (fixed by setup_inputs)
#define BQ   8
#define SEQ  1024
#define CH   512
#define HIDC 2048
#define NHD  8
#define HDIM 64
#define ROWS (BQ*SEQ)          // 8192
#define QKVW (3*CH)            // 1536

// ---------------- scratch (device globals; no allocations allowed) ---------
__device__ float g_ln [ROWS*CH];
__device__ float g_qkv[ROWS*QKVW];
__device__ float g_at [ROWS*CH];
__device__ float g_x1 [ROWS*CH];
__device__ float g_h  [ROWS*HIDC];
__device__ float g_h2 [ROWS*HIDC];

// ---------------- LayerNorm -------------------------------------------------
__global__ void ln_kernel(const float* __restrict__ x,
                          const float* __restrict__ g,
                          const float* __restrict__ b,
                          float* __restrict__ out)
{
    int row = blockIdx.x;
    const float* xr = x + (size_t)row * CH;
    float*       orow = out + (size_t)row * CH;
    int t = threadIdx.x;
    float v[4];
    float s = 0.f;
#pragma unroll
    for (int i = 0; i < 4; i++) { v[i] = xr[t + i*128]; s += v[i]; }
    __shared__ float red[4];
#pragma unroll
    for (int o = 16; o > 0; o >>= 1) s += __shfl_xor_sync(0xffffffffu, s, o);
    if ((t & 31) == 0) red[t >> 5] = s;
    __syncthreads();
    float mean = (red[0] + red[1] + red[2] + red[3]) * (1.0f / CH);
    float vs = 0.f;
#pragma unroll
    for (int i = 0; i < 4; i++) { float d = v[i] - mean; vs += d * d; }
#pragma unroll
    for (int o = 16; o > 0; o >>= 1) vs += __shfl_xor_sync(0xffffffffu, vs, o);
    __syncthreads();
    if ((t & 31) == 0) red[t >> 5] = vs;
    __syncthreads();
    float var = (red[0] + red[1] + red[2] + red[3]) * (1.0f / CH);
    float rstd = rsqrtf(var + 1e-5f);
#pragma unroll
    for (int i = 0; i < 4; i++) {
        int c = t + i*128;
        orow[c] = (v[i] - mean) * rstd * g[c] + b[c];
    }
}

// ---------------- tf32 WMMA GEMM: out = A @ B^T ----------------------------
// A [M,K] row-major, B [N,K] row-major (so matrix_b col_major over [k][n]).
// CTA tile 128x128, 256 threads = 8 warps in 2(m) x 4(n); warp tile 64x32.
#define WG_M 128
#define WG_N 128
#define WG_K 32
#define LDS  36   // padded ld (36 floats = 144 B, multiple of 16 B)

__global__ __launch_bounds__(256)
void gemm_wmma(const float* __restrict__ A, int lda,
               const float* __restrict__ B, int ldb,
               float* __restrict__ out, int ldo, int K)
{
    __shared__ float As[WG_M][LDS];
    __shared__ float Bs[WG_N][LDS];

    int tid = threadIdx.x;
    int wid = tid >> 5;
    int wm = wid >> 2;          // 0..1
    int wn = wid & 3;           // 0..3
    int m0 = blockIdx.y * WG_M;
    int n0 = blockIdx.x * WG_N;

    wmma::fragment<wmma::accumulator, 16, 16, 8, float> fc[4][2];
#pragma unroll
    for (int i = 0; i < 4; i++)
#pragma unroll
        for (int j = 0; j < 2; j++)
            wmma::fill_fragment(fc[i][j], 0.0f);

    int lrow = tid >> 3;            // 0..31
    int lq   = (tid & 7) * 4;       // 0,4,...,28

    for (int k0 = 0; k0 < K; k0 += WG_K) {
#pragma unroll
        for (int p = 0; p < 4; p++) {
            int r = lrow + p * 32;
            *(float4*)&As[r][lq] = *(const float4*)(A + (size_t)(m0 + r) * lda + k0 + lq);
            *(float4*)&Bs[r][lq] = *(const float4*)(B + (size_t)(n0 + r) * ldb + k0 + lq);
        }
        __syncthreads();

#pragma unroll
        for (int ks = 0; ks < WG_K / 8; ks++) {
            wmma::fragment<wmma::matrix_a, 16, 16, 8, wmma::precision::tf32, wmma::row_major> fa[4];
            wmma::fragment<wmma::matrix_b, 16, 16, 8, wmma::precision::tf32, wmma::col_major> fb[2];
#pragma unroll
            for (int i = 0; i < 4; i++) {
                wmma::load_matrix_sync(fa[i], &As[wm * 64 + i * 16][ks * 8], LDS);
#pragma unroll
                for (int t = 0; t < fa[i].num_elements; t++)
                    fa[i].x[t] = wmma::__float_to_tf32(fa[i].x[t]);
            }
#pragma unroll
            for (int j = 0; j < 2; j++) {
                wmma::load_matrix_sync(fb[j], &Bs[wn * 32 + j * 16][ks * 8], LDS);
#pragma unroll
                for (int t = 0; t < fb[j].num_elements; t++)
                    fb[j].x[t] = wmma::__float_to_tf32(fb[j].x[t]);
            }
#pragma unroll
            for (int i = 0; i < 4; i++)
#pragma unroll
                for (int j = 0; j < 2; j++)
                    wmma::mma_sync(fc[i][j], fa[i], fb[j], fc[i][j]);
        }
        __syncthreads();
    }

#pragma unroll
    for (int i = 0; i < 4; i++)
#pragma unroll
        for (int j = 0; j < 2; j++)
            wmma::store_matrix_sync(
                out + (size_t)(m0 + wm * 64 + i * 16) * ldo + n0 + wn * 32 + j * 16,
                fc[i][j], ldo, wmma::mem_row_major);
}

// ---------------- epilogues (bias / bias+residual) -------------------------
__global__ void ep_bias(float* __restrict__ out, const float* __restrict__ bias, int N)
{
    size_t idx = ((size_t)blockIdx.x * 256 + threadIdx.x) * 4;
    int n = (int)(idx % N);
    float4 v = *(float4*)(out + idx);
    v.x += bias[n]; v.y += bias[n + 1]; v.z += bias[n + 2]; v.w += bias[n + 3];
    *(float4*)(out + idx) = v;
}
__global__ void ep_bias_res(float* __restrict__ out, const float* __restrict__ bias,
                            const float* __restrict__ res, int N)
{
    size_t idx = ((size_t)blockIdx.x * 256 + threadIdx.x) * 4;
    int n = (int)(idx % N);
    float4 v = *(float4*)(out + idx);
    float4 r = *(const float4*)(res + idx);
    v.x += bias[n]     + r.x;
    v.y += bias[n + 1] + r.y;
    v.z += bias[n + 2] + r.z;
    v.w += bias[n + 3] + r.w;
    *(float4*)(out + idx) = v;
}

// ---------------- Fused flash attention (fp32, proven in R3) ---------------
#define PADW 68
#define OFF_Q  0
#define OFF_K  (64*PADW)
#define OFF_P  (2*64*PADW)
#define OFF_V  (3*64*PADW)
#define FLASH_SMEM_BYTES ((3*64*PADW + 64*64)*4)

__global__ __launch_bounds__(256)
void flash_kernel(const float* __restrict__ qkv, float* __restrict__ out)
{
    extern __shared__ float smf[];
    float* Qs = smf + OFF_Q;
    float* Ks = smf + OFF_K;
    float* Pt = smf + OFF_P;
    float* Vs = smf + OFF_V;

    int bz = blockIdx.y;
    int bI = bz / NHD, hI = bz % NHD;
    int q0 = blockIdx.x * 64;
    const float* base = qkv + (size_t)bI * SEQ * QKVW + hI * 3 * HDIM;

    int tid = threadIdx.x;
    int ty = tid >> 4, tx = tid & 15;
    int lm = tid >> 2;
    int kq = (tid & 3) * 4;

#pragma unroll
    for (int r = 0; r < 4; r++) {
        int d = kq + r * 16;
        float4 a4 = *(const float4*)(base + (size_t)(q0 + lm) * QKVW + d);
        Qs[(d + 0) * PADW + lm] = a4.x; Qs[(d + 1) * PADW + lm] = a4.y;
        Qs[(d + 2) * PADW + lm] = a4.z; Qs[(d + 3) * PADW + lm] = a4.w;
    }

    float m[4], l[4], o[4][4];
#pragma unroll
    for (int i = 0; i < 4; i++) {
        m[i] = -1e30f; l[i] = 0.f;
#pragma unroll
        for (int j = 0; j < 4; j++) o[i][j] = 0.f;
    }

    for (int t0 = 0; t0 < SEQ; t0 += 64) {
        __syncthreads();
#pragma unroll
        for (int r = 0; r < 4; r++) {
            int d = kq + r * 16;
            float4 k4 = *(const float4*)(base + (size_t)(t0 + lm) * QKVW + HDIM + d);
            Ks[(d + 0) * PADW + lm] = k4.x; Ks[(d + 1) * PADW + lm] = k4.y;
            Ks[(d + 2) * PADW + lm] = k4.z; Ks[(d + 3) * PADW + lm] = k4.w;
            float4 v4 = *(const float4*)(base + (size_t)(t0 + lm) * QKVW + 2 * HDIM + d);
            *(float4*)&Vs[lm * 64 + d] = v4;
        }
        __syncthreads();

        float s[4][4] = {};
#pragma unroll
        for (int kk = 0; kk < 64; kk++) {
            float4 qv = *(const float4*)&Qs[kk * PADW + ty * 4];
            float4 kv = *(const float4*)&Ks[kk * PADW + tx * 4];
            float qa[4] = {qv.x, qv.y, qv.z, qv.w};
            float kb[4] = {kv.x, kv.y, kv.z, kv.w};
#pragma unroll
            for (int i = 0; i < 4; i++)
#pragma unroll
                for (int j = 0; j < 4; j++)
                    s[i][j] += qa[i] * kb[j];
        }

        float rmax[4], rsum[4];
#pragma unroll
        for (int i = 0; i < 4; i++) {
            float mx = s[i][0];
#pragma unroll
            for (int j = 1; j < 4; j++) mx = fmaxf(mx, s[i][j]);
            rmax[i] = mx * 0.125f;
        }
#pragma unroll
        for (int msk = 1; msk < 16; msk <<= 1)
#pragma unroll
            for (int i = 0; i < 4; i++)
                rmax[i] = fmaxf(rmax[i], __shfl_xor_sync(0xffffffffu, rmax[i], msk));

#pragma unroll
        for (int i = 0; i < 4; i++) {
            float mnew = fmaxf(m[i], rmax[i]);
            float scale = __expf(m[i] - mnew);
            m[i] = mnew;
            l[i] *= scale;
            float su = 0.f;
#pragma unroll
            for (int j = 0; j < 4; j++) {
                float p = __expf(s[i][j] * 0.125f - mnew);
                s[i][j] = p;
                su += p;
            }
            rsum[i] = su;
#pragma unroll
            for (int j = 0; j < 4; j++) o[i][j] *= scale;
        }
#pragma unroll
        for (int msk = 1; msk < 16; msk <<= 1)
#pragma unroll
            for (int i = 0; i < 4; i++)
                rsum[i] += __shfl_xor_sync(0xffffffffu, rsum[i], msk);
#pragma unroll
        for (int i = 0; i < 4; i++) l[i] += rsum[i];

#pragma unroll
        for (int i = 0; i < 4; i++)
#pragma unroll
            for (int j = 0; j < 4; j++)
                Pt[(tx * 4 + j) * PADW + ty * 4 + i] = s[i][j];
        __syncthreads();

#pragma unroll
        for (int kk = 0; kk < 64; kk++) {
            float4 pv = *(const float4*)&Pt[kk * PADW + ty * 4];
            float4 vv = *(const float4*)&Vs[kk * 64 + tx * 4];
            float pa[4] = {pv.x, pv.y, pv.z, pv.w};
            float vb[4] = {vv.x, vv.y, vv.z, vv.w};
#pragma unroll
            for (int i = 0; i < 4; i++)
#pragma unroll
                for (int j = 0; j < 4; j++)
                    o[i][j] += pa[i] * vb[j];
        }
    }

#pragma unroll
    for (int i = 0; i < 4; i++) {
        int q = q0 + ty * 4 + i;
        float inv = 1.0f / l[i];
        float* op = out + ((size_t)bI * SEQ + q) * CH + hI * HDIM + tx * 4;
#pragma unroll
        for (int j = 0; j < 4; j++) op[j] = o[i][j] * inv;
    }
}

// ---------------- Depthwise 3x3 conv + exact GELU --------------------------
__global__ void dwgelu_kernel(const float* __restrict__ h,
                              const float* __restrict__ w,
                              const float* __restrict__ bias,
                              float* __restrict__ out)
{
    int c = blockIdx.x * 256 + threadIdx.x;
    int n = blockIdx.y;
    int b = blockIdx.z;
    int hh = n >> 5, ww = n & 31;
    float acc = bias[c];
#pragma unroll
    for (int dy = -1; dy <= 1; dy++) {
        int y = hh + dy;
        if (y < 0 || y >= 32) continue;
#pragma unroll
        for (int dx = -1; dx <= 1; dx++) {
            int xw = ww + dx;
            if (xw < 0 || xw >= 32) continue;
            acc += h[((size_t)b * SEQ + y * 32 + xw) * HIDC + c]
                 * w[c * 9 + (dy + 1) * 3 + (dx + 1)];
        }
    }
    float gv = 0.5f * acc * (1.0f + erff(acc * 0.70710678118654752f));
    out[((size_t)b * SEQ + n) * HIDC + c] = gv;
}

// ---------------- launch ----------------------------------------------------
extern "C" void kernel_launch(void* const* d_in, const int* in_sizes, int n_in,
                              void* d_out, int out_size)
{
    const float* x      = (const float*)d_in[0];
    const float* ln1_g  = (const float*)d_in[1];
    const float* ln1_b  = (const float*)d_in[2];
    const float* qkv_w  = (const float*)d_in[3];
    const float* proj_w = (const float*)d_in[4];
    const float* proj_b = (const float*)d_in[5];
    const float* ln2_g  = (const float*)d_in[6];
    const float* ln2_b  = (const float*)d_in[7];
    const float* fc1_w  = (const float*)d_in[8];
    const float* fc1_b  = (const float*)d_in[9];
    const float* dw_w   = (const float*)d_in[10];
    const float* dw_b   = (const float*)d_in[11];
    const float* fc2_w  = (const float*)d_in[12];
    const float* fc2_b  = (const float*)d_in[13];
    float* out = (float*)d_out;

    float *lnb, *qkvb, *atb, *x1b, *hb, *h2b;
    cudaGetSymbolAddress((void**)&lnb,  g_ln);
    cudaGetSymbolAddress((void**)&qkvb, g_qkv);
    cudaGetSymbolAddress((void**)&atb,  g_at);
    cudaGetSymbolAddress((void**)&x1b,  g_x1);
    cudaGetSymbolAddress((void**)&hb,   g_h);
    cudaGetSymbolAddress((void**)&h2b,  g_h2);

    cudaFuncSetAttribute(flash_kernel,
                         cudaFuncAttributeMaxDynamicSharedMemorySize,
                         FLASH_SMEM_BYTES);

    // 1) LN1
    ln_kernel<<<ROWS, 128>>>(x, ln1_g, ln1_b, lnb);

    // 2) QKV GEMM (tf32 wmma): [8192,1536] = ln @ qkv_w^T
    gemm_wmma<<<dim3(QKVW/WG_N, ROWS/WG_M), 256>>>(lnb, CH, qkv_w, CH, qkvb, QKVW, CH);

    // 3) fused attention -> atb [8192, 512]
    flash_kernel<<<dim3(SEQ/64, BQ*NHD), 256, FLASH_SMEM_BYTES>>>(qkvb, atb);

    // 4) x1 = o @ proj_w^T ; += proj_b + x
    gemm_wmma<<<dim3(CH/WG_N, ROWS/WG_M), 256>>>(atb, CH, proj_w, CH, x1b, CH, CH);
    ep_bias_res<<<(ROWS*CH)/1024, 256>>>(x1b, proj_b, x, CH);

    // 5) LN2
    ln_kernel<<<ROWS, 128>>>(x1b, ln2_g, ln2_b, lnb);

    // 6) h = ln2 @ fc1_w^T ; += fc1_b
    gemm_wmma<<<dim3(HIDC/WG_N, ROWS/WG_M), 256>>>(lnb, CH, fc1_w, CH, hb, HIDC, CH);
    ep_bias<<<(ROWS*HIDC)/1024, 256>>>(hb, fc1_b, HIDC);

    // 7) depthwise conv 3x3 + bias + exact gelu
    dwgelu_kernel<<<dim3(HIDC/256, SEQ, BQ), 256>>>(hb, dw_w, dw_b, h2b);

    // 8) out = h2 @ fc2_w^T ; += fc2_b + x1
    gemm_wmma<<<dim3(CH/WG_N, ROWS/WG_M), 256>>>(h2b, HIDC, fc2_w, HIDC, out, CH, HIDC);
    ep_bias_res<<<(ROWS*CH)/1024, 256>>>(out, fc2_b, x1b, CH);
}

// round 8
// speedup vs baseline: 1.5159x; 1.1004x over previous
#include <cuda_runtime.h>
#include <mma.h>
#include <math.h>
#include <stdint.h>

using namespace nvcuda;

// Problem constants (fixed by setup_inputs)
#define BQ   8
#define SEQ  1024
#define CH   512
#define HIDC 2048
#define NHD  8
#define HDIM 64
#define ROWS (BQ*SEQ)          // 8192
#define QKVW (3*CH)            // 1536

// ---------------- scratch (device globals; no allocations allowed) ---------
__device__ float g_ln [ROWS*CH];
__device__ float g_qkv[ROWS*QKVW];
__device__ float g_at [ROWS*CH];
__device__ float g_x1 [ROWS*CH];
__device__ float g_h  [ROWS*HIDC];
__device__ float g_h2 [ROWS*HIDC];

// ---------------- helpers ---------------------------------------------------
__device__ __forceinline__ uint32_t su32(const void* p) {
    uint32_t a;
    asm("{ .reg .u64 t; cvta.to.shared.u64 t, %1; cvt.u32.u64 %0, t; }"
        : "=r"(a) : "l"(p));
    return a;
}
#define CPA16(d, s) asm volatile("cp.async.cg.shared.global [%0], [%1], 16;" :: "r"(d), "l"(s))
#define CPCOMMIT()  asm volatile("cp.async.commit_group;" ::: "memory")
#define CPWAIT(n)   asm volatile("cp.async.wait_group %0;" :: "n"(n) : "memory")

// ---------------- LayerNorm -------------------------------------------------
__global__ void ln_kernel(const float* __restrict__ x,
                          const float* __restrict__ g,
                          const float* __restrict__ b,
                          float* __restrict__ out)
{
    int row = blockIdx.x;
    const float* xr = x + (size_t)row * CH;
    float*       orow = out + (size_t)row * CH;
    int t = threadIdx.x;
    float v[4];
    float s = 0.f;
#pragma unroll
    for (int i = 0; i < 4; i++) { v[i] = xr[t + i*128]; s += v[i]; }
    __shared__ float red[4];
#pragma unroll
    for (int o = 16; o > 0; o >>= 1) s += __shfl_xor_sync(0xffffffffu, s, o);
    if ((t & 31) == 0) red[t >> 5] = s;
    __syncthreads();
    float mean = (red[0] + red[1] + red[2] + red[3]) * (1.0f / CH);
    float vs = 0.f;
#pragma unroll
    for (int i = 0; i < 4; i++) { float d = v[i] - mean; vs += d * d; }
#pragma unroll
    for (int o = 16; o > 0; o >>= 1) vs += __shfl_xor_sync(0xffffffffu, vs, o);
    __syncthreads();
    if ((t & 31) == 0) red[t >> 5] = vs;
    __syncthreads();
    float var = (red[0] + red[1] + red[2] + red[3]) * (1.0f / CH);
    float rstd = rsqrtf(var + 1e-5f);
#pragma unroll
    for (int i = 0; i < 4; i++) {
        int c = t + i*128;
        orow[c] = (v[i] - mean) * rstd * g[c] + b[c];
    }
}

// ---------------- tf32 WMMA GEMM, cp.async double-buffered ------------------
// out = A @ B^T (+bias)(+res). A [M,K] rm, B [N,K] rm.
// CTA 128x128, 8 warps (2m x 4n), warp 64x32. Dynamic smem.
#define LDS 36
#define TILE_F (128*LDS)            // floats per tile buffer
#define GT_SMEM (4*TILE_F*4)        // 2 bufs x (A+B) = 73728 bytes

__global__ __launch_bounds__(256, 2)
void gemm_wmma(const float* __restrict__ A, int lda,
               const float* __restrict__ B, int ldb,
               const float* __restrict__ bias,
               const float* __restrict__ res, int ldres,
               float* __restrict__ out, int ldo, int K)
{
    extern __shared__ float dsm[];
    float* As = dsm;                // [2][128][LDS]
    float* Bs = dsm + 2*TILE_F;

    int tid = threadIdx.x;
    int wid = tid >> 5;
    int wm = wid >> 2;
    int wn = wid & 3;
    int m0 = blockIdx.y * 128;
    int n0 = blockIdx.x * 128;

    wmma::fragment<wmma::accumulator, 16, 16, 8, float> fc[4][2];
#pragma unroll
    for (int i = 0; i < 4; i++)
#pragma unroll
        for (int j = 0; j < 2; j++)
            wmma::fill_fragment(fc[i][j], 0.0f);

    int lrow = tid >> 3;
    int lq   = (tid & 7) * 4;

    int nK = K / 32;

    // prologue: issue tile 0
#pragma unroll
    for (int p = 0; p < 4; p++) {
        int r = lrow + p * 32;
        CPA16(su32(&As[r * LDS + lq]), A + (size_t)(m0 + r) * lda + lq);
        CPA16(su32(&Bs[r * LDS + lq]), B + (size_t)(n0 + r) * ldb + lq);
    }
    CPCOMMIT();

    for (int kc = 0; kc < nK; kc++) {
        int cur = kc & 1;
        if (kc + 1 < nK) {
            int nxt = cur ^ 1;
            int k0 = (kc + 1) * 32;
#pragma unroll
            for (int p = 0; p < 4; p++) {
                int r = lrow + p * 32;
                CPA16(su32(&As[nxt * TILE_F + r * LDS + lq]),
                      A + (size_t)(m0 + r) * lda + k0 + lq);
                CPA16(su32(&Bs[nxt * TILE_F + r * LDS + lq]),
                      B + (size_t)(n0 + r) * ldb + k0 + lq);
            }
            CPCOMMIT();
            CPWAIT(1);
        } else {
            CPWAIT(0);
        }
        __syncthreads();

        float* Ac = As + cur * TILE_F;
        float* Bc = Bs + cur * TILE_F;
#pragma unroll
        for (int ks = 0; ks < 4; ks++) {
            wmma::fragment<wmma::matrix_a, 16, 16, 8, wmma::precision::tf32, wmma::row_major> fa[4];
            wmma::fragment<wmma::matrix_b, 16, 16, 8, wmma::precision::tf32, wmma::col_major> fb[2];
#pragma unroll
            for (int i = 0; i < 4; i++) {
                wmma::load_matrix_sync(fa[i], &Ac[(wm * 64 + i * 16) * LDS + ks * 8], LDS);
#pragma unroll
                for (int t = 0; t < fa[i].num_elements; t++)
                    fa[i].x[t] = wmma::__float_to_tf32(fa[i].x[t]);
            }
#pragma unroll
            for (int j = 0; j < 2; j++) {
                wmma::load_matrix_sync(fb[j], &Bc[(wn * 32 + j * 16) * LDS + ks * 8], LDS);
#pragma unroll
                for (int t = 0; t < fb[j].num_elements; t++)
                    fb[j].x[t] = wmma::__float_to_tf32(fb[j].x[t]);
            }
#pragma unroll
            for (int i = 0; i < 4; i++)
#pragma unroll
                for (int j = 0; j < 2; j++)
                    wmma::mma_sync(fc[i][j], fa[i], fb[j], fc[i][j]);
        }
        __syncthreads();
    }

    // epilogue: stage tile in smem (reuse dsm), fuse bias/res, write out
#pragma unroll
    for (int i = 0; i < 4; i++)
#pragma unroll
        for (int j = 0; j < 2; j++)
            wmma::store_matrix_sync(&dsm[(wm * 64 + i * 16) * 128 + wn * 32 + j * 16],
                                    fc[i][j], 128, wmma::mem_row_major);
    __syncthreads();

    int r = tid >> 1;
    int c0 = (tid & 1) * 64;
#pragma unroll
    for (int c = 0; c < 64; c += 4) {
        float4 v = *(float4*)&dsm[r * 128 + c0 + c];
        int n = n0 + c0 + c;
        if (bias) {
            v.x += bias[n]; v.y += bias[n + 1]; v.z += bias[n + 2]; v.w += bias[n + 3];
        }
        if (res) {
            float4 rr = *(const float4*)(res + (size_t)(m0 + r) * ldres + n);
            v.x += rr.x; v.y += rr.y; v.z += rr.z; v.w += rr.w;
        }
        *(float4*)(out + (size_t)(m0 + r) * ldo + n) = v;
    }
}

// ---------------- Flash attention with wmma tf32 ----------------------------
// CTA: 64 queries x one head; 256 threads (8 warps). S and PV on tensor cores.
#define FPAD 68
#define FQ  0
#define FK  (64*FPAD)
#define FV  (2*64*FPAD)
#define FS  (3*64*FPAD)
#define FO  (4*64*FPAD)
#define FML (5*64*FPAD)
#define FLASH_SMEM ((5*64*FPAD + 128) * 4)

__global__ __launch_bounds__(256, 2)
void flash_wmma(const float* __restrict__ qkv, float* __restrict__ out)
{
    extern __shared__ float fs[];
    float* Qs = fs + FQ;
    float* Ks = fs + FK;
    float* Vs = fs + FV;
    float* Ss = fs + FS;
    float* Os = fs + FO;
    float* m_s = fs + FML;
    float* l_s = m_s + 64;

    int bz = blockIdx.y;
    int bI = bz / NHD, hI = bz % NHD;
    int q0 = blockIdx.x * 64;
    const float* base = qkv + (size_t)bI * SEQ * QKVW + hI * 3 * HDIM;

    int tid = threadIdx.x;
    int wid = tid >> 5;
    int lrow = tid >> 2;            // 0..63
    int lc0  = (tid & 3) * 16;      // 0,16,32,48

    // load Q tile, zero O, init m/l
    {
        const float* src = base + (size_t)(q0 + lrow) * QKVW + lc0;
#pragma unroll
        for (int c = 0; c < 16; c += 4) {
            *(float4*)&Qs[lrow * FPAD + lc0 + c] = *(const float4*)(src + c);
            float4 z = {0.f, 0.f, 0.f, 0.f};
            *(float4*)&Os[lrow * FPAD + lc0 + c] = z;
        }
        if (tid < 64) { m_s[tid] = -1e30f; l_s[tid] = 0.f; }
    }

    for (int t0 = 0; t0 < SEQ; t0 += 64) {
        __syncthreads();
        // load K, V tiles
        {
            const float* kp = base + (size_t)(t0 + lrow) * QKVW + HDIM + lc0;
            const float* vp = base + (size_t)(t0 + lrow) * QKVW + 2 * HDIM + lc0;
#pragma unroll
            for (int c = 0; c < 16; c += 4) {
                *(float4*)&Ks[lrow * FPAD + lc0 + c] = *(const float4*)(kp + c);
                *(float4*)&Vs[lrow * FPAD + lc0 + c] = *(const float4*)(vp + c);
            }
        }
        __syncthreads();

        // S = Q @ K^T  (64x64); 8 warps x 2 tiles of 16x16
#pragma unroll
        for (int t = 0; t < 2; t++) {
            int tt = wid * 2 + t;
            int ti = tt >> 2, tj = tt & 3;
            wmma::fragment<wmma::accumulator, 16, 16, 8, float> sc;
            wmma::fill_fragment(sc, 0.0f);
#pragma unroll
            for (int kf = 0; kf < 8; kf++) {
                wmma::fragment<wmma::matrix_a, 16, 16, 8, wmma::precision::tf32, wmma::row_major> fa;
                wmma::fragment<wmma::matrix_b, 16, 16, 8, wmma::precision::tf32, wmma::col_major> fb;
                wmma::load_matrix_sync(fa, &Qs[(ti * 16) * FPAD + kf * 8], FPAD);
                wmma::load_matrix_sync(fb, &Ks[(tj * 16) * FPAD + kf * 8], FPAD);
#pragma unroll
                for (int e = 0; e < fa.num_elements; e++) fa.x[e] = wmma::__float_to_tf32(fa.x[e]);
#pragma unroll
                for (int e = 0; e < fb.num_elements; e++) fb.x[e] = wmma::__float_to_tf32(fb.x[e]);
                wmma::mma_sync(sc, fa, fb, sc);
            }
            wmma::store_matrix_sync(&Ss[(ti * 16) * FPAD + tj * 16], sc, FPAD, wmma::mem_row_major);
        }
        __syncthreads();

        // online softmax: 4 threads per row (same warp quad)
        {
            float* srow = &Ss[lrow * FPAD + lc0];
            float mx = -1e30f;
#pragma unroll
            for (int c = 0; c < 16; c++) mx = fmaxf(mx, srow[c]);
            mx *= 0.125f;
            mx = fmaxf(mx, __shfl_xor_sync(0xffffffffu, mx, 1));
            mx = fmaxf(mx, __shfl_xor_sync(0xffffffffu, mx, 2));
            float mold = m_s[lrow];
            float mnew = fmaxf(mold, mx);
            float sf = __expf(mold - mnew);
            float sum = 0.f;
#pragma unroll
            for (int c = 0; c < 16; c++) {
                float p = __expf(srow[c] * 0.125f - mnew);
                srow[c] = p;
                sum += p;
            }
            sum += __shfl_xor_sync(0xffffffffu, sum, 1);
            sum += __shfl_xor_sync(0xffffffffu, sum, 2);
            float* orow = &Os[lrow * FPAD + lc0];
#pragma unroll
            for (int c = 0; c < 16; c++) orow[c] *= sf;
            if ((tid & 3) == 0) {
                m_s[lrow] = mnew;
                l_s[lrow] = l_s[lrow] * sf + sum;
            }
        }
        __syncthreads();

        // O += P @ V
#pragma unroll
        for (int t = 0; t < 2; t++) {
            int tt = wid * 2 + t;
            int ti = tt >> 2, tj = tt & 3;
            wmma::fragment<wmma::accumulator, 16, 16, 8, float> oc;
            wmma::load_matrix_sync(oc, &Os[(ti * 16) * FPAD + tj * 16], FPAD, wmma::mem_row_major);
#pragma unroll
            for (int kf = 0; kf < 8; kf++) {
                wmma::fragment<wmma::matrix_a, 16, 16, 8, wmma::precision::tf32, wmma::row_major> fa;
                wmma::fragment<wmma::matrix_b, 16, 16, 8, wmma::precision::tf32, wmma::row_major> fb;
                wmma::load_matrix_sync(fa, &Ss[(ti * 16) * FPAD + kf * 8], FPAD);
                wmma::load_matrix_sync(fb, &Vs[(kf * 8) * FPAD + tj * 16], FPAD);
#pragma unroll
                for (int e = 0; e < fa.num_elements; e++) fa.x[e] = wmma::__float_to_tf32(fa.x[e]);
#pragma unroll
                for (int e = 0; e < fb.num_elements; e++) fb.x[e] = wmma::__float_to_tf32(fb.x[e]);
                wmma::mma_sync(oc, fa, fb, oc);
            }
            wmma::store_matrix_sync(&Os[(ti * 16) * FPAD + tj * 16], oc, FPAD, wmma::mem_row_major);
        }
    }
    __syncthreads();

    // writeout: O / l
    {
        float inv = 1.0f / l_s[lrow];
        float* op = out + ((size_t)bI * SEQ + q0 + lrow) * CH + hI * HDIM + lc0;
#pragma unroll
        for (int c = 0; c < 16; c += 4) {
            float4 v = *(float4*)&Os[lrow * FPAD + lc0 + c];
            v.x *= inv; v.y *= inv; v.z *= inv; v.w *= inv;
            *(float4*)(op + c) = v;
        }
    }
}

// ---------------- Depthwise 3x3 conv + exact GELU --------------------------
__global__ void dwgelu_kernel(const float* __restrict__ h,
                              const float* __restrict__ w,
                              const float* __restrict__ bias,
                              float* __restrict__ out)
{
    int c = blockIdx.x * 256 + threadIdx.x;
    int n = blockIdx.y;
    int b = blockIdx.z;
    int hh = n >> 5, ww = n & 31;
    float acc = bias[c];
#pragma unroll
    for (int dy = -1; dy <= 1; dy++) {
        int y = hh + dy;
        if (y < 0 || y >= 32) continue;
#pragma unroll
        for (int dx = -1; dx <= 1; dx++) {
            int xw = ww + dx;
            if (xw < 0 || xw >= 32) continue;
            acc += h[((size_t)b * SEQ + y * 32 + xw) * HIDC + c]
                 * w[c * 9 + (dy + 1) * 3 + (dx + 1)];
        }
    }
    float gv = 0.5f * acc * (1.0f + erff(acc * 0.70710678118654752f));
    out[((size_t)b * SEQ + n) * HIDC + c] = gv;
}

// ---------------- launch ----------------------------------------------------
extern "C" void kernel_launch(void* const* d_in, const int* in_sizes, int n_in,
                              void* d_out, int out_size)
{
    const float* x      = (const float*)d_in[0];
    const float* ln1_g  = (const float*)d_in[1];
    const float* ln1_b  = (const float*)d_in[2];
    const float* qkv_w  = (const float*)d_in[3];
    const float* proj_w = (const float*)d_in[4];
    const float* proj_b = (const float*)d_in[5];
    const float* ln2_g  = (const float*)d_in[6];
    const float* ln2_b  = (const float*)d_in[7];
    const float* fc1_w  = (const float*)d_in[8];
    const float* fc1_b  = (const float*)d_in[9];
    const float* dw_w   = (const float*)d_in[10];
    const float* dw_b   = (const float*)d_in[11];
    const float* fc2_w  = (const float*)d_in[12];
    const float* fc2_b  = (const float*)d_in[13];
    float* out = (float*)d_out;

    float *lnb, *qkvb, *atb, *x1b, *hb, *h2b;
    cudaGetSymbolAddress((void**)&lnb,  g_ln);
    cudaGetSymbolAddress((void**)&qkvb, g_qkv);
    cudaGetSymbolAddress((void**)&atb,  g_at);
    cudaGetSymbolAddress((void**)&x1b,  g_x1);
    cudaGetSymbolAddress((void**)&hb,   g_h);
    cudaGetSymbolAddress((void**)&h2b,  g_h2);

    cudaFuncSetAttribute(gemm_wmma,
                         cudaFuncAttributeMaxDynamicSharedMemorySize, GT_SMEM);
    cudaFuncSetAttribute(flash_wmma,
                         cudaFuncAttributeMaxDynamicSharedMemorySize, FLASH_SMEM);

    // 1) LN1
    ln_kernel<<<ROWS, 128>>>(x, ln1_g, ln1_b, lnb);

    // 2) QKV GEMM: [8192,1536] = ln @ qkv_w^T
    gemm_wmma<<<dim3(QKVW/128, ROWS/128), 256, GT_SMEM>>>(
        lnb, CH, qkv_w, CH, nullptr, nullptr, 0, qkvb, QKVW, CH);

    // 3) fused attention -> atb [8192, 512]
    flash_wmma<<<dim3(SEQ/64, BQ*NHD), 256, FLASH_SMEM>>>(qkvb, atb);

    // 4) x1 = x + o @ proj_w^T + proj_b
    gemm_wmma<<<dim3(CH/128, ROWS/128), 256, GT_SMEM>>>(
        atb, CH, proj_w, CH, proj_b, x, CH, x1b, CH, CH);

    // 5) LN2
    ln_kernel<<<ROWS, 128>>>(x1b, ln2_g, ln2_b, lnb);

    // 6) h = ln2 @ fc1_w^T + fc1_b
    gemm_wmma<<<dim3(HIDC/128, ROWS/128), 256, GT_SMEM>>>(
        lnb, CH, fc1_w, CH, fc1_b, nullptr, 0, hb, HIDC, CH);

    // 7) depthwise conv 3x3 + bias + exact gelu
    dwgelu_kernel<<<dim3(HIDC/256, SEQ, BQ), 256>>>(hb, dw_w, dw_b, h2b);

    // 8) out = x1 + h2 @ fc2_w^T + fc2_b
    gemm_wmma<<<dim3(CH/128, ROWS/128), 256, GT_SMEM>>>(
        h2b, HIDC, fc2_w, HIDC, fc2_b, x1b, CH, out, CH, HIDC);
}

// round 10
// speedup vs baseline: 3.0444x; 2.0083x over previous
#include <cuda_runtime.h>
#include <cuda_bf16.h>
#include <mma.h>
#include <math.h>
#include <stdint.h>

using namespace nvcuda;
typedef __nv_bfloat16 bf16;

// Problem constants
#define BQ   8
#define SEQ  1024
#define CH   512
#define HIDC 2048
#define NHD  8
#define HDIM 64
#define ROWS (BQ*SEQ)          // 8192
#define QKVW (3*CH)            // 1536

// ---------------- scratch ----------------------------------------------------
__device__ bf16  g_wqkv[QKVW*CH];
__device__ bf16  g_wproj[CH*CH];
__device__ bf16  g_wfc1[HIDC*CH];
__device__ bf16  g_wfc2[CH*HIDC];
__device__ bf16  g_ln16[ROWS*CH];
__device__ bf16  g_qkv16[(size_t)ROWS*QKVW];
__device__ bf16  g_at16[ROWS*CH];
__device__ float g_x1 [ROWS*CH];
__device__ bf16  g_h16 [(size_t)ROWS*HIDC];
__device__ bf16  g_h216[(size_t)ROWS*HIDC];

// ---------------- helpers ---------------------------------------------------
__device__ __forceinline__ uint32_t su32(const void* p) {
    uint32_t a;
    asm("{ .reg .u64 t; cvta.to.shared.u64 t, %1; cvt.u32.u64 %0, t; }"
        : "=r"(a) : "l"(p));
    return a;
}
#define CPA16(d, s) asm volatile("cp.async.cg.shared.global [%0], [%1], 16;" :: "r"(d), "l"(s))
#define CPCOMMIT()  asm volatile("cp.async.commit_group;" ::: "memory")
#define CPWAIT(n)   asm volatile("cp.async.wait_group %0;" :: "n"(n) : "memory")

// ---------------- fp32 -> bf16 convert --------------------------------------
__global__ void to_bf16(const float* __restrict__ s, bf16* __restrict__ d)
{
    size_t i = ((size_t)blockIdx.x * 256 + threadIdx.x) * 4;
    float4 v = *(const float4*)(s + i);
    bf16 t[4] = { __float2bfloat16(v.x), __float2bfloat16(v.y),
                  __float2bfloat16(v.z), __float2bfloat16(v.w) };
    *(uint2*)(d + i) = *(uint2*)t;
}

// ---------------- LayerNorm (fp32 in, bf16 out) -----------------------------
__global__ void ln_kernel(const float* __restrict__ x,
                          const float* __restrict__ g,
                          const float* __restrict__ b,
                          bf16* __restrict__ out)
{
    int row = blockIdx.x;
    const float* xr = x + (size_t)row * CH;
    bf16* orow = out + (size_t)row * CH;
    int t = threadIdx.x;
    float v[4];
    float s = 0.f;
#pragma unroll
    for (int i = 0; i < 4; i++) { v[i] = xr[t + i*128]; s += v[i]; }
    __shared__ float red[4];
#pragma unroll
    for (int o = 16; o > 0; o >>= 1) s += __shfl_xor_sync(0xffffffffu, s, o);
    if ((t & 31) == 0) red[t >> 5] = s;
    __syncthreads();
    float mean = (red[0] + red[1] + red[2] + red[3]) * (1.0f / CH);
    float vs = 0.f;
#pragma unroll
    for (int i = 0; i < 4; i++) { float d = v[i] - mean; vs += d * d; }
#pragma unroll
    for (int o = 16; o > 0; o >>= 1) vs += __shfl_xor_sync(0xffffffffu, vs, o);
    __syncthreads();
    if ((t & 31) == 0) red[t >> 5] = vs;
    __syncthreads();
    float var = (red[0] + red[1] + red[2] + red[3]) * (1.0f / CH);
    float rstd = rsqrtf(var + 1e-5f);
#pragma unroll
    for (int i = 0; i < 4; i++) {
        int c = t + i*128;
        orow[c] = __float2bfloat16((v[i] - mean) * rstd * g[c] + b[c]);
    }
}

// ---------------- bf16 WMMA GEMM, cp.async double-buffered ------------------
// out = A @ B^T (+bias)(+res). A [M,K] bf16 rm, B [N,K] bf16 rm.
// CTA 128x128, 8 warps (2m x 4n), warp 64x32. K-chunk 64.
#define LDSB 72                 // bf16 elems per smem row (144B)
#define TILE_E (128*LDSB)       // elems per tile buffer
#define GT_SMEM (4*TILE_E*2)    // 2 bufs x (A+B) x 2B = 73728

template<typename OutT>
__global__ __launch_bounds__(256, 2)
void gemm_bf(const bf16* __restrict__ A, int lda,
             const bf16* __restrict__ B, int ldb,
             const float* __restrict__ bias,
             const float* __restrict__ res, int ldres,
             OutT* __restrict__ out, int ldo, int K)
{
    extern __shared__ char dsmc[];
    bf16* As = (bf16*)dsmc;              // [2][128][LDSB]
    bf16* Bs = As + 2*TILE_E;

    int tid = threadIdx.x;
    int wid = tid >> 5;
    int wm = wid >> 2;
    int wn = wid & 3;
    int m0 = blockIdx.y * 128;
    int n0 = blockIdx.x * 128;

    wmma::fragment<wmma::accumulator, 16, 16, 16, float> fc[4][2];
#pragma unroll
    for (int i = 0; i < 4; i++)
#pragma unroll
        for (int j = 0; j < 2; j++)
            wmma::fill_fragment(fc[i][j], 0.0f);

    int lrow  = tid >> 1;               // 0..127
    int sbase = (tid & 1) * 4;          // seg base (8 elems each)

    int nK = K / 64;

#pragma unroll
    for (int j = 0; j < 4; j++) {
        int cseg = (sbase + j) * 8;
        CPA16(su32(&As[lrow * LDSB + cseg]), A + (size_t)(m0 + lrow) * lda + cseg);
        CPA16(su32(&Bs[lrow * LDSB + cseg]), B + (size_t)(n0 + lrow) * ldb + cseg);
    }
    CPCOMMIT();

    for (int kc = 0; kc < nK; kc++) {
        int cur = kc & 1;
        if (kc + 1 < nK) {
            int nxt = cur ^ 1;
            int k0 = (kc + 1) * 64;
#pragma unroll
            for (int j = 0; j < 4; j++) {
                int cseg = (sbase + j) * 8;
                CPA16(su32(&As[nxt * TILE_E + lrow * LDSB + cseg]),
                      A + (size_t)(m0 + lrow) * lda + k0 + cseg);
                CPA16(su32(&Bs[nxt * TILE_E + lrow * LDSB + cseg]),
                      B + (size_t)(n0 + lrow) * ldb + k0 + cseg);
            }
            CPCOMMIT();
            CPWAIT(1);
        } else {
            CPWAIT(0);
        }
        __syncthreads();

        bf16* Ac = As + cur * TILE_E;
        bf16* Bc = Bs + cur * TILE_E;
#pragma unroll
        for (int ks = 0; ks < 4; ks++) {
            wmma::fragment<wmma::matrix_a, 16, 16, 16, bf16, wmma::row_major> fa[4];
            wmma::fragment<wmma::matrix_b, 16, 16, 16, bf16, wmma::col_major> fb[2];
#pragma unroll
            for (int i = 0; i < 4; i++)
                wmma::load_matrix_sync(fa[i], &Ac[(wm * 64 + i * 16) * LDSB + ks * 16], LDSB);
#pragma unroll
            for (int j = 0; j < 2; j++)
                wmma::load_matrix_sync(fb[j], &Bc[(wn * 32 + j * 16) * LDSB + ks * 16], LDSB);
#pragma unroll
            for (int i = 0; i < 4; i++)
#pragma unroll
                for (int j = 0; j < 2; j++)
                    wmma::mma_sync(fc[i][j], fa[i], fb[j], fc[i][j]);
        }
        __syncthreads();
    }

    // epilogue through smem (reuse tile space), fused bias/res
    float* eps = (float*)dsmc;          // [128][132]
#pragma unroll
    for (int i = 0; i < 4; i++)
#pragma unroll
        for (int j = 0; j < 2; j++)
            wmma::store_matrix_sync(&eps[(wm * 64 + i * 16) * 132 + wn * 32 + j * 16],
                                    fc[i][j], 132, wmma::mem_row_major);
    __syncthreads();

    int r = tid >> 1;
    int c0 = (tid & 1) * 64;
#pragma unroll
    for (int c = 0; c < 64; c += 4) {
        float4 v = *(float4*)&eps[r * 132 + c0 + c];
        int n = n0 + c0 + c;
        if (bias) {
            v.x += bias[n]; v.y += bias[n + 1]; v.z += bias[n + 2]; v.w += bias[n + 3];
        }
        if (res) {
            float4 rr = *(const float4*)(res + (size_t)(m0 + r) * ldres + n);
            v.x += rr.x; v.y += rr.y; v.z += rr.z; v.w += rr.w;
        }
        if constexpr (sizeof(OutT) == 4) {
            *(float4*)((float*)out + (size_t)(m0 + r) * ldo + n) = v;
        } else {
            bf16 t[4] = { __float2bfloat16(v.x), __float2bfloat16(v.y),
                          __float2bfloat16(v.z), __float2bfloat16(v.w) };
            *(uint2*)((bf16*)out + (size_t)(m0 + r) * ldo + n) = *(uint2*)t;
        }
    }
}

// ---------------- Flash attention, bf16 wmma --------------------------------
// CTA: 64 queries x one head; 256 threads (8 warps).
#define FQS  0
#define FKS  (64*LDSB*2)
#define FVS  (2*64*LDSB*2)
#define FPB  (3*64*LDSB*2)
#define FSS  (4*64*LDSB*2)              // fp32 [64][68]
#define FOS  (FSS + 64*68*4)
#define FMLX (FOS + 64*68*4)
#define FLASH_SMEM (FMLX + 512)

__global__ __launch_bounds__(256, 2)
void flash_bf(const bf16* __restrict__ qkv, bf16* __restrict__ out)
{
    extern __shared__ char fsc[];
    bf16*  Qs = (bf16*)(fsc + FQS);     // [64][LDSB]
    bf16*  Ks = (bf16*)(fsc + FKS);
    bf16*  Vs = (bf16*)(fsc + FVS);
    bf16*  Pb = (bf16*)(fsc + FPB);
    float* Ss = (float*)(fsc + FSS);    // [64][68]
    float* Os = (float*)(fsc + FOS);    // [64][68]
    float* m_s = (float*)(fsc + FMLX);
    float* l_s = m_s + 64;

    int bz = blockIdx.y;
    int bI = bz / NHD, hI = bz % NHD;
    int q0 = blockIdx.x * 64;
    const bf16* base = qkv + (size_t)bI * SEQ * QKVW + hI * 3 * HDIM;

    int tid = threadIdx.x;
    int wid = tid >> 5;
    int lrow = tid >> 2;                // 0..63
    int lc0  = (tid & 3) * 16;          // 0,16,32,48

    {
        const bf16* src = base + (size_t)(q0 + lrow) * QKVW + lc0;
        *(uint4*)&Qs[lrow * LDSB + lc0]     = *(const uint4*)(src);
        *(uint4*)&Qs[lrow * LDSB + lc0 + 8] = *(const uint4*)(src + 8);
        float4 z = {0.f, 0.f, 0.f, 0.f};
        *(float4*)&Os[lrow * 68 + lc0]      = z;
        *(float4*)&Os[lrow * 68 + lc0 + 4]  = z;
        *(float4*)&Os[lrow * 68 + lc0 + 8]  = z;
        *(float4*)&Os[lrow * 68 + lc0 + 12] = z;
        if (tid < 64) { m_s[tid] = -1e30f; l_s[tid] = 0.f; }
    }

    for (int t0 = 0; t0 < SEQ; t0 += 64) {
        __syncthreads();
        {
            const bf16* kp = base + (size_t)(t0 + lrow) * QKVW + HDIM + lc0;
            const bf16* vp = base + (size_t)(t0 + lrow) * QKVW + 2 * HDIM + lc0;
            *(uint4*)&Ks[lrow * LDSB + lc0]     = *(const uint4*)(kp);
            *(uint4*)&Ks[lrow * LDSB + lc0 + 8] = *(const uint4*)(kp + 8);
            *(uint4*)&Vs[lrow * LDSB + lc0]     = *(const uint4*)(vp);
            *(uint4*)&Vs[lrow * LDSB + lc0 + 8] = *(const uint4*)(vp + 8);
        }
        __syncthreads();

        // S = Q @ K^T  (64x64, K=64): 8 warps x 2 tiles
#pragma unroll
        for (int t = 0; t < 2; t++) {
            int tt = wid * 2 + t;
            int ti = tt >> 2, tj = tt & 3;
            wmma::fragment<wmma::accumulator, 16, 16, 16, float> sc;
            wmma::fill_fragment(sc, 0.0f);
#pragma unroll
            for (int kf = 0; kf < 4; kf++) {
                wmma::fragment<wmma::matrix_a, 16, 16, 16, bf16, wmma::row_major> fa;
                wmma::fragment<wmma::matrix_b, 16, 16, 16, bf16, wmma::col_major> fb;
                wmma::load_matrix_sync(fa, &Qs[(ti * 16) * LDSB + kf * 16], LDSB);
                wmma::load_matrix_sync(fb, &Ks[(tj * 16) * LDSB + kf * 16], LDSB);
                wmma::mma_sync(sc, fa, fb, sc);
            }
            wmma::store_matrix_sync(&Ss[(ti * 16) * 68 + tj * 16], sc, 68, wmma::mem_row_major);
        }
        __syncthreads();

        // online softmax (fp32), write P to bf16
        {
            float* srow = &Ss[lrow * 68 + lc0];
            float mx = -1e30f;
#pragma unroll
            for (int c = 0; c < 16; c++) mx = fmaxf(mx, srow[c]);
            mx *= 0.125f;
            mx = fmaxf(mx, __shfl_xor_sync(0xffffffffu, mx, 1));
            mx = fmaxf(mx, __shfl_xor_sync(0xffffffffu, mx, 2));
            float mold = m_s[lrow];
            float mnew = fmaxf(mold, mx);
            float sf = __expf(mold - mnew);
            float sum = 0.f;
            bf16* prow = &Pb[lrow * LDSB + lc0];
#pragma unroll
            for (int c = 0; c < 16; c++) {
                float p = __expf(srow[c] * 0.125f - mnew);
                prow[c] = __float2bfloat16(p);
                sum += p;
            }
            sum += __shfl_xor_sync(0xffffffffu, sum, 1);
            sum += __shfl_xor_sync(0xffffffffu, sum, 2);
            float* orow = &Os[lrow * 68 + lc0];
#pragma unroll
            for (int c = 0; c < 16; c++) orow[c] *= sf;
            if ((tid & 3) == 0) {
                m_s[lrow] = mnew;
                l_s[lrow] = l_s[lrow] * sf + sum;
            }
        }
        __syncthreads();

        // O += P @ V (K=64)
#pragma unroll
        for (int t = 0; t < 2; t++) {
            int tt = wid * 2 + t;
            int ti = tt >> 2, tj = tt & 3;
            wmma::fragment<wmma::accumulator, 16, 16, 16, float> oc;
            wmma::load_matrix_sync(oc, &Os[(ti * 16) * 68 + tj * 16], 68, wmma::mem_row_major);
#pragma unroll
            for (int kf = 0; kf < 4; kf++) {
                wmma::fragment<wmma::matrix_a, 16, 16, 16, bf16, wmma::row_major> fa;
                wmma::fragment<wmma::matrix_b, 16, 16, 16, bf16, wmma::row_major> fb;
                wmma::load_matrix_sync(fa, &Pb[(ti * 16) * LDSB + kf * 16], LDSB);
                wmma::load_matrix_sync(fb, &Vs[(kf * 16) * LDSB + tj * 16], LDSB);
                wmma::mma_sync(oc, fa, fb, oc);
            }
            wmma::store_matrix_sync(&Os[(ti * 16) * 68 + tj * 16], oc, 68, wmma::mem_row_major);
        }
    }
    __syncthreads();

    {
        float inv = 1.0f / l_s[lrow];
        bf16* op = out + ((size_t)bI * SEQ + q0 + lrow) * CH + hI * HDIM + lc0;
#pragma unroll
        for (int c = 0; c < 16; c += 2) {
            bf16 t2[2] = { __float2bfloat16(Os[lrow * 68 + lc0 + c] * inv),
                           __float2bfloat16(Os[lrow * 68 + lc0 + c + 1] * inv) };
            *(uint32_t*)(op + c) = *(uint32_t*)t2;
        }
    }
}

// ---------------- Depthwise 3x3 conv + exact GELU (bf16 io) -----------------
__global__ void dwgelu_kernel(const bf16* __restrict__ h,
                              const float* __restrict__ w,
                              const float* __restrict__ bias,
                              bf16* __restrict__ out)
{
    int c = blockIdx.x * 256 + threadIdx.x;
    int n = blockIdx.y;
    int b = blockIdx.z;
    int hh = n >> 5, ww = n & 31;
    float acc = bias[c];
#pragma unroll
    for (int dy = -1; dy <= 1; dy++) {
        int y = hh + dy;
        if (y < 0 || y >= 32) continue;
#pragma unroll
        for (int dx = -1; dx <= 1; dx++) {
            int xw = ww + dx;
            if (xw < 0 || xw >= 32) continue;
            acc += __bfloat162float(h[((size_t)b * SEQ + y * 32 + xw) * HIDC + c])
                 * w[c * 9 + (dy + 1) * 3 + (dx + 1)];
        }
    }
    float gv = 0.5f * acc * (1.0f + erff(acc * 0.70710678118654752f));
    out[((size_t)b * SEQ + n) * HIDC + c] = __float2bfloat16(gv);
}

// ---------------- launch ----------------------------------------------------
extern "C" void kernel_launch(void* const* d_in, const int* in_sizes, int n_in,
                              void* d_out, int out_size)
{
    const float* x      = (const float*)d_in[0];
    const float* ln1_g  = (const float*)d_in[1];
    const float* ln1_b  = (const float*)d_in[2];
    const float* qkv_w  = (const float*)d_in[3];
    const float* proj_w = (const float*)d_in[4];
    const float* proj_b = (const float*)d_in[5];
    const float* ln2_g  = (const float*)d_in[6];
    const float* ln2_b  = (const float*)d_in[7];
    const float* fc1_w  = (const float*)d_in[8];
    const float* fc1_b  = (const float*)d_in[9];
    const float* dw_w   = (const float*)d_in[10];
    const float* dw_b   = (const float*)d_in[11];
    const float* fc2_w  = (const float*)d_in[12];
    const float* fc2_b  = (const float*)d_in[13];
    float* out = (float*)d_out;

    bf16 *wqkv, *wproj, *wfc1, *wfc2, *ln16, *qkv16, *at16, *h16, *h216;
    float *x1b;
    cudaGetSymbolAddress((void**)&wqkv,  g_wqkv);
    cudaGetSymbolAddress((void**)&wproj, g_wproj);
    cudaGetSymbolAddress((void**)&wfc1,  g_wfc1);
    cudaGetSymbolAddress((void**)&wfc2,  g_wfc2);
    cudaGetSymbolAddress((void**)&ln16,  g_ln16);
    cudaGetSymbolAddress((void**)&qkv16, g_qkv16);
    cudaGetSymbolAddress((void**)&at16,  g_at16);
    cudaGetSymbolAddress((void**)&x1b,   g_x1);
    cudaGetSymbolAddress((void**)&h16,   g_h16);
    cudaGetSymbolAddress((void**)&h216,  g_h216);

    cudaFuncSetAttribute(gemm_bf<float>,
                         cudaFuncAttributeMaxDynamicSharedMemorySize, GT_SMEM);
    cudaFuncSetAttribute(gemm_bf<bf16>,
                         cudaFuncAttributeMaxDynamicSharedMemorySize, GT_SMEM);
    cudaFuncSetAttribute(flash_bf,
                         cudaFuncAttributeMaxDynamicSharedMemorySize, FLASH_SMEM);

    // 0) weight conversion (fp32 -> bf16)
    to_bf16<<<(QKVW*CH)/1024, 256>>>(qkv_w,  wqkv);
    to_bf16<<<(CH*CH)/1024,   256>>>(proj_w, wproj);
    to_bf16<<<(HIDC*CH)/1024, 256>>>(fc1_w,  wfc1);
    to_bf16<<<(CH*HIDC)/1024, 256>>>(fc2_w,  wfc2);

    // 1) LN1 -> bf16
    ln_kernel<<<ROWS, 128>>>(x, ln1_g, ln1_b, ln16);

    // 2) QKV GEMM -> bf16
    gemm_bf<bf16><<<dim3(QKVW/128, ROWS/128), 256, GT_SMEM>>>(
        ln16, CH, wqkv, CH, nullptr, nullptr, 0, qkv16, QKVW, CH);

    // 3) flash attention -> bf16
    flash_bf<<<dim3(SEQ/64, BQ*NHD), 256, FLASH_SMEM>>>(qkv16, at16);

    // 4) x1 = x + o @ proj_w^T + proj_b   (fp32 out)
    gemm_bf<float><<<dim3(CH/128, ROWS/128), 256, GT_SMEM>>>(
        at16, CH, wproj, CH, proj_b, x, CH, x1b, CH, CH);

    // 5) LN2 -> bf16
    ln_kernel<<<ROWS, 128>>>(x1b, ln2_g, ln2_b, ln16);

    // 6) h = ln2 @ fc1_w^T + fc1_b -> bf16
    gemm_bf<bf16><<<dim3(HIDC/128, ROWS/128), 256, GT_SMEM>>>(
        ln16, CH, wfc1, CH, fc1_b, nullptr, 0, h16, HIDC, CH);

    // 7) depthwise conv + gelu -> bf16
    dwgelu_kernel<<<dim3(HIDC/256, SEQ, BQ), 256>>>(h16, dw_w, dw_b, h216);

    // 8) out = x1 + h2 @ fc2_w^T + fc2_b  (fp32 out)
    gemm_bf<float><<<dim3(CH/128, ROWS/128), 256, GT_SMEM>>>(
        h216, HIDC, wfc2, HIDC, fc2_b, x1b, CH, out, CH, HIDC);
}